// round 11
// baseline (speedup 1.0000x reference)
#include <cuda_runtime.h>
#include <cuda_bf16.h>
#include <cstdint>

#define PP 5
#define BLK 256
#define UBV 0.5f
#define LBV 0.0f

__device__ __forceinline__ float tanh_fast(float x) {
    float y;
    asm("tanh.approx.f32 %0, %1;" : "=f"(y) : "f"(x));
    return y;
}

// R7 configuration — measured optimum (23.0 us).
// R9 (forced 8 CTAs/SM): spills, 26.1 us. R10 (hoisted cov store): broke
// inter-CTA tail/stage overlap, 33.3 us. Tail store + natural regalloc wins.
__global__ __launch_bounds__(BLK) void portfolio_kernel(
    const float* __restrict__ x1,    // (B,)
    const float* __restrict__ x2,    // (B,5,5)
    const float* __restrict__ eps,   // (4,B,5)
    const float* __restrict__ W,     // (4,3,5,5)
    float* __restrict__ out_wealth,  // (B,)
    float* __restrict__ out_cov,     // (B,5,5)
    int B, int vec_ok)
{
    // 16B alignment REQUIRED for float4 shared paths (R2/R3 trap without it).
    __shared__ __align__(16) float s_x2[BLK * 25];  // staged x2, rewritten as curr_cov
    __shared__ __align__(16) float s_eps[BLK * 5];  // staged eps[3]
    __shared__ float s_w[75];                        // W[3]: 3 matrices of 5x5

    const int tid = threadIdx.x;
    const long long base = (long long)blockIdx.x * BLK;

    // Prefetch x1 early — independent LDG overlaps the staging latency.
    const float x1v = x1[base + tid];

    if (tid < 75) s_w[tid] = W[3 * 75 + tid];

    // Coalesced staging of this block's x2 tile and eps[3] tile.
    const float* __restrict__ x2g  = x2 + base * 25;
    const float* __restrict__ epsg = eps + (long long)3 * B * PP + base * PP;
    if (vec_ok) {
        const float4* __restrict__ g4 = (const float4*)x2g;
        float4* s4 = (float4*)s_x2;
        #pragma unroll
        for (int j = tid; j < BLK * 25 / 4; j += BLK) s4[j] = g4[j];
        const float4* __restrict__ e4 = (const float4*)epsg;
        float4* se4 = (float4*)s_eps;
        for (int j = tid; j < BLK * 5 / 4; j += BLK) se4[j] = e4[j];
    } else {
        #pragma unroll 4
        for (int j = tid; j < BLK * 25; j += BLK) s_x2[j] = x2g[j];
        for (int j = tid; j < BLK * 5; j += BLK) s_eps[j] = epsg[j];
    }
    __syncthreads();

    // Ce = x2_row @ eps3  (stride-25 shared reads: 25 coprime 32 -> conflict-free)
    float e[PP];
    #pragma unroll
    for (int i = 0; i < PP; i++) e[i] = s_eps[tid * PP + i];

    float ce[PP];
    {
        float m2[25];
        #pragma unroll
        for (int i = 0; i < 25; i++) m2[i] = s_x2[tid * 25 + i];
        #pragma unroll
        for (int i = 0; i < PP; i++) {
            float s = 0.f;
            #pragma unroll
            for (int j = 0; j < PP; j++) s += m2[i * PP + j] * e[j];
            ce[i] = s;
        }
        // curr_cov = omega + alpha*x2 + beta*Ce[j]^2 — write into own shared row
        // NOW so the 25 m2 registers die before the MLP (register pressure).
        float cb[PP];
        #pragma unroll
        for (int j = 0; j < PP; j++) cb[j] = 0.05f + 0.05f * ce[j] * ce[j];
        #pragma unroll
        for (int i = 0; i < PP; i++)
            #pragma unroll
            for (int j = 0; j < PP; j++)
                s_x2[tid * 25 + i * PP + j] = fmaf(0.1f, m2[i * PP + j], cb[j]);
    }

    // R = mu + Ce ; h = R then 3x tanh(h @ W_l^T)
    float r[PP], h[PP];
    #pragma unroll
    for (int i = 0; i < PP; i++) { r[i] = 0.01f + ce[i]; h[i] = r[i]; }
    #pragma unroll
    for (int l = 0; l < 3; l++) {
        float t[PP];
        #pragma unroll
        for (int i = 0; i < PP; i++) {
            float s = 0.f;
            #pragma unroll
            for (int j = 0; j < PP; j++) s += h[j] * s_w[l * 25 + i * PP + j];
            t[i] = tanh_fast(s);
        }
        #pragma unroll
        for (int i = 0; i < PP; i++) h[i] = t[i];
    }

    // softmax with max subtraction, single fast reciprocal
    float mx = h[0];
    #pragma unroll
    for (int i = 1; i < PP; i++) mx = fmaxf(mx, h[i]);
    float ssum = 0.f;
    float wgt[PP];
    #pragma unroll
    for (int i = 0; i < PP; i++) { wgt[i] = __expf(h[i] - mx); ssum += wgt[i]; }
    const float sinv = __fdividef(1.f, ssum);
    #pragma unroll
    for (int i = 0; i < PP; i++) wgt[i] *= sinv;

    // --- rebalance: semantics-exact replication of the 8-iter scan.
    // Once cont==false the reference freezes this row, so breaking is exact.
    float oldw[PP], nw[PP];
    #pragma unroll
    for (int i = 0; i < PP; i++) {
        oldw[i] = wgt[i];
        nw[i]  = fminf(fmaxf(wgt[i], LBV), UBV);
    }
    for (int it = 0; it < 8; it++) {
        float leftover = 0.f, msum = 0.f;
        float masked[PP];
        #pragma unroll
        for (int i = 0; i < PP; i++) {
            leftover += oldw[i] - nw[i];
            masked[i] = (nw[i] != UBV) ? nw[i] : 0.f;
            msum += masked[i];
        }
        const float scale = __fdividef(leftover, msum);
        float new2[PP];
        bool cont = false;
        #pragma unroll
        for (int i = 0; i < PP; i++) {
            new2[i] = fmaf(scale, masked[i], nw[i]);
            cont = cont || (new2[i] > UBV);
        }
        #pragma unroll
        for (int i = 0; i < PP; i++) {
            oldw[i] = new2[i];
            nw[i]   = cont ? fminf(fmaxf(new2[i], LBV), UBV) : new2[i];
        }
        if (!cont) break;
    }

    // wealth — evict-first store (output is never re-read; keep L2 for inputs)
    float wealth = 0.f;
    #pragma unroll
    for (int i = 0; i < PP; i++) wealth += x1v * nw[i] * (1.f + r[i]) * 1.03f;
    __stcs(out_wealth + base + tid, wealth);

    __syncthreads();
    // Coalesced evict-first store of curr_cov. Streaming the 54.6 MB of output
    // keeps the 65 MB input set resident in L2 across graph replays. Tail
    // placement is deliberate: the drain overlaps other resident CTAs' work.
    float* __restrict__ covg = out_cov + base * 25;
    if (vec_ok) {
        float4* __restrict__ c4 = (float4*)covg;
        const float4* s4 = (const float4*)s_x2;
        #pragma unroll
        for (int j = tid; j < BLK * 25 / 4; j += BLK) __stcs(c4 + j, s4[j]);
    } else {
        #pragma unroll 4
        for (int j = tid; j < BLK * 25; j += BLK) __stcs(covg + j, s_x2[j]);
    }
}

extern "C" void kernel_launch(void* const* d_in, const int* in_sizes, int n_in,
                              void* d_out, int out_size) {
    const float* x1  = (const float*)d_in[0];   // (B,)
    const float* x2  = (const float*)d_in[1];   // (B,5,5)
    const float* eps = (const float*)d_in[2];   // (4,B,5)
    const float* W   = (const float*)d_in[3];   // (4,3,5,5)
    float* out = (float*)d_out;                 // [wealth(B) | curr_cov(B*25)]

    const int B = in_sizes[0];
    float* out_wealth = out;
    float* out_cov    = out + B;

    // Vector path only if every float4-accessed global stream is 16B aligned.
    // (B is a multiple of BLK=256, so all in-kernel offsets preserve alignment.)
    const int vec_ok =
        (((uintptr_t)x2      & 15) == 0) &&
        (((uintptr_t)eps     & 15) == 0) &&
        (((uintptr_t)out_cov & 15) == 0) ? 1 : 0;

    portfolio_kernel<<<B / BLK, BLK>>>(x1, x2, eps, W, out_wealth, out_cov, B, vec_ok);
}

// round 12
// speedup vs baseline: 1.3483x; 1.3483x over previous
#include <cuda_runtime.h>
#include <cuda_bf16.h>
#include <cstdint>

#define PP 5
#define BLK 256
#define UBV 0.5f
#define LBV 0.0f

__device__ __forceinline__ float tanh_fast(float x) {
    float y;
    asm("tanh.approx.f32 %0, %1;" : "=f"(y) : "f"(x));
    return y;
}

// R7 structure (measured optimum; R9 forced-occupancy and R10 store-hoist both
// regressed). R11 A/A test showed ~40% environment drift on identical SASS, so
// this round makes a strictly-work-removing change only: curr_cov is fused into
// the tail store loop (cov STS round eliminated; s_x2 stays pristine x2).
__global__ __launch_bounds__(BLK) void portfolio_kernel(
    const float* __restrict__ x1,    // (B,)
    const float* __restrict__ x2,    // (B,5,5)
    const float* __restrict__ eps,   // (4,B,5)
    const float* __restrict__ W,     // (4,3,5,5)
    float* __restrict__ out_wealth,  // (B,)
    float* __restrict__ out_cov,     // (B,5,5)
    int B, int vec_ok)
{
    // 16B alignment REQUIRED for float4 shared paths (R2/R3 trap without it).
    __shared__ __align__(16) float s_x2[BLK * 25];   // staged x2 (never rewritten)
    __shared__ __align__(16) float s_eps[BLK * 5];   // staged eps[3]; reused as cb
    __shared__ float s_w[75];                         // W[3]: 3 matrices of 5x5

    const int tid = threadIdx.x;
    const long long base = (long long)blockIdx.x * BLK;

    // Prefetch x1 early — independent LDG overlaps the staging latency.
    const float x1v = x1[base + tid];

    if (tid < 75) s_w[tid] = W[3 * 75 + tid];

    // Coalesced staging of this block's x2 tile and eps[3] tile.
    const float* __restrict__ x2g  = x2 + base * 25;
    const float* __restrict__ epsg = eps + (long long)3 * B * PP + base * PP;
    if (vec_ok) {
        const float4* __restrict__ g4 = (const float4*)x2g;
        float4* s4 = (float4*)s_x2;
        #pragma unroll
        for (int j = tid; j < BLK * 25 / 4; j += BLK) s4[j] = g4[j];
        const float4* __restrict__ e4 = (const float4*)epsg;
        float4* se4 = (float4*)s_eps;
        for (int j = tid; j < BLK * 5 / 4; j += BLK) se4[j] = e4[j];
    } else {
        #pragma unroll 4
        for (int j = tid; j < BLK * 25; j += BLK) s_x2[j] = x2g[j];
        for (int j = tid; j < BLK * 5; j += BLK) s_eps[j] = epsg[j];
    }
    __syncthreads();

    // Ce = x2_row @ eps3  (stride-25/5 shared reads: coprime 32 -> conflict-free)
    float e[PP];
    #pragma unroll
    for (int i = 0; i < PP; i++) e[i] = s_eps[tid * PP + i];

    float ce[PP];
    {
        float m2[25];
        #pragma unroll
        for (int i = 0; i < 25; i++) m2[i] = s_x2[tid * 25 + i];
        #pragma unroll
        for (int i = 0; i < PP; i++) {
            float s = 0.f;
            #pragma unroll
            for (int j = 0; j < PP; j++) s += m2[i * PP + j] * e[j];
            ce[i] = s;
        }
    }
    // cb[j] = omega + beta*Ce[j]^2 — 5 STS into this thread's OWN s_eps row
    // (already consumed into e[] by this thread only; no cross-thread hazard,
    // so no barrier needed here). Tail loop reads it after the tail barrier.
    float* __restrict__ s_cb = s_eps;
    #pragma unroll
    for (int j = 0; j < PP; j++)
        s_cb[tid * PP + j] = 0.05f + 0.05f * ce[j] * ce[j];

    // R = mu + Ce ; h = R then 3x tanh(h @ W_l^T)
    float r[PP], h[PP];
    #pragma unroll
    for (int i = 0; i < PP; i++) { r[i] = 0.01f + ce[i]; h[i] = r[i]; }
    #pragma unroll
    for (int l = 0; l < 3; l++) {
        float t[PP];
        #pragma unroll
        for (int i = 0; i < PP; i++) {
            float s = 0.f;
            #pragma unroll
            for (int j = 0; j < PP; j++) s += h[j] * s_w[l * 25 + i * PP + j];
            t[i] = tanh_fast(s);
        }
        #pragma unroll
        for (int i = 0; i < PP; i++) h[i] = t[i];
    }

    // softmax with max subtraction, single fast reciprocal
    float mx = h[0];
    #pragma unroll
    for (int i = 1; i < PP; i++) mx = fmaxf(mx, h[i]);
    float ssum = 0.f;
    float wgt[PP];
    #pragma unroll
    for (int i = 0; i < PP; i++) { wgt[i] = __expf(h[i] - mx); ssum += wgt[i]; }
    const float sinv = __fdividef(1.f, ssum);
    #pragma unroll
    for (int i = 0; i < PP; i++) wgt[i] *= sinv;

    // --- rebalance: semantics-exact replication of the 8-iter scan.
    // Once cont==false the reference freezes this row, so breaking is exact.
    float oldw[PP], nw[PP];
    #pragma unroll
    for (int i = 0; i < PP; i++) {
        oldw[i] = wgt[i];
        nw[i]  = fminf(fmaxf(wgt[i], LBV), UBV);
    }
    for (int it = 0; it < 8; it++) {
        float leftover = 0.f, msum = 0.f;
        float masked[PP];
        #pragma unroll
        for (int i = 0; i < PP; i++) {
            leftover += oldw[i] - nw[i];
            masked[i] = (nw[i] != UBV) ? nw[i] : 0.f;
            msum += masked[i];
        }
        const float scale = __fdividef(leftover, msum);
        float new2[PP];
        bool cont = false;
        #pragma unroll
        for (int i = 0; i < PP; i++) {
            new2[i] = fmaf(scale, masked[i], nw[i]);
            cont = cont || (new2[i] > UBV);
        }
        #pragma unroll
        for (int i = 0; i < PP; i++) {
            oldw[i] = new2[i];
            nw[i]   = cont ? fminf(fmaxf(new2[i], LBV), UBV) : new2[i];
        }
        if (!cont) break;
    }

    // wealth — evict-first store (output is never re-read; keep L2 for inputs)
    float wealth = 0.f;
    #pragma unroll
    for (int i = 0; i < PP; i++) wealth += x1v * nw[i] * (1.f + r[i]) * 1.03f;
    __stcs(out_wealth + base + tid, wealth);

    __syncthreads();
    // Tail store: cov computed on the fly from pristine staged x2 + cb.
    // Element ji -> sample ji/25, column ji%5 (25 is a multiple of 5), so
    // cb index = (ji/25)*5 + ji%5. Evict-first keeps inputs L2-resident
    // across graph replays (the R7 win); tail placement preserves the
    // inter-CTA drain/stage overlap (R10 lesson).
    float* __restrict__ covg = out_cov + base * 25;
    if (vec_ok) {
        float4* __restrict__ c4 = (float4*)covg;
        const float4* sx4 = (const float4*)s_x2;
        #pragma unroll
        for (int j4 = tid; j4 < BLK * 25 / 4; j4 += BLK) {
            float4 v = sx4[j4];
            const int ji = j4 * 4;
            const float cb0 = s_cb[((ji + 0) / 25) * PP + ((ji + 0) % PP)];
            const float cb1 = s_cb[((ji + 1) / 25) * PP + ((ji + 1) % PP)];
            const float cb2 = s_cb[((ji + 2) / 25) * PP + ((ji + 2) % PP)];
            const float cb3 = s_cb[((ji + 3) / 25) * PP + ((ji + 3) % PP)];
            v.x = fmaf(0.1f, v.x, cb0);
            v.y = fmaf(0.1f, v.y, cb1);
            v.z = fmaf(0.1f, v.z, cb2);
            v.w = fmaf(0.1f, v.w, cb3);
            __stcs(c4 + j4, v);
        }
    } else {
        #pragma unroll 4
        for (int j = tid; j < BLK * 25; j += BLK) {
            const float cb = s_cb[(j / 25) * PP + (j % PP)];
            __stcs(covg + j, fmaf(0.1f, s_x2[j], cb));
        }
    }
}

extern "C" void kernel_launch(void* const* d_in, const int* in_sizes, int n_in,
                              void* d_out, int out_size) {
    const float* x1  = (const float*)d_in[0];   // (B,)
    const float* x2  = (const float*)d_in[1];   // (B,5,5)
    const float* eps = (const float*)d_in[2];   // (4,B,5)
    const float* W   = (const float*)d_in[3];   // (4,3,5,5)
    float* out = (float*)d_out;                 // [wealth(B) | curr_cov(B*25)]

    const int B = in_sizes[0];
    float* out_wealth = out;
    float* out_cov    = out + B;

    // Vector path only if every float4-accessed global stream is 16B aligned.
    // (B is a multiple of BLK=256, so all in-kernel offsets preserve alignment.)
    const int vec_ok =
        (((uintptr_t)x2      & 15) == 0) &&
        (((uintptr_t)eps     & 15) == 0) &&
        (((uintptr_t)out_cov & 15) == 0) ? 1 : 0;

    portfolio_kernel<<<B / BLK, BLK>>>(x1, x2, eps, W, out_wealth, out_cov, B, vec_ok);
}

// round 13
// speedup vs baseline: 1.5261x; 1.1319x over previous
#include <cuda_runtime.h>
#include <cuda_bf16.h>
#include <cstdint>

#define PP 5
#define BLK 256
#define UBV 0.5f
#define LBV 0.0f

__device__ __forceinline__ float tanh_fast(float x) {
    float y;
    asm("tanh.approx.f32 %0, %1;" : "=f"(y) : "f"(x));
    return y;
}

// R7 structure — the instruction-lean schedule (issue ~29%):
//   R9  forced occupancy -> spills, regression
//   R10 hoisted cov store -> broke inter-CTA overlap, regression
//   R12 cov fusion -> +170 ALU/thread of index math, issue 50.8%, regression
// This round: R7 minus the s_eps staging (direct 5x LDG.32 per thread).
__global__ __launch_bounds__(BLK) void portfolio_kernel(
    const float* __restrict__ x1,    // (B,)
    const float* __restrict__ x2,    // (B,5,5)
    const float* __restrict__ eps,   // (4,B,5)
    const float* __restrict__ W,     // (4,3,5,5)
    float* __restrict__ out_wealth,  // (B,)
    float* __restrict__ out_cov,     // (B,5,5)
    int B, int vec_ok)
{
    // 16B alignment REQUIRED for float4 shared paths (R2/R3 trap without it).
    __shared__ __align__(16) float s_x2[BLK * 25];  // staged x2, rewritten as curr_cov
    __shared__ float s_w[75];                        // W[3]: 3 matrices of 5x5

    const int tid = threadIdx.x;
    const long long base = (long long)blockIdx.x * BLK;

    // Prefetch x1 early — independent LDG overlaps the staging latency.
    const float x1v = x1[base + tid];

    // Direct per-thread eps[3] row load (5x LDG.32, 20B stride; L2-resident on
    // warm replays). Issued before staging so latency overlaps the x2 tile load.
    const float* __restrict__ epsg = eps + (long long)3 * B * PP + (base + tid) * PP;
    float e[PP];
    #pragma unroll
    for (int i = 0; i < PP; i++) e[i] = epsg[i];

    if (tid < 75) s_w[tid] = W[3 * 75 + tid];

    // Coalesced staging of this block's x2 tile.
    const float* __restrict__ x2g = x2 + base * 25;
    if (vec_ok) {
        const float4* __restrict__ g4 = (const float4*)x2g;
        float4* s4 = (float4*)s_x2;
        #pragma unroll
        for (int j = tid; j < BLK * 25 / 4; j += BLK) s4[j] = g4[j];
    } else {
        #pragma unroll 4
        for (int j = tid; j < BLK * 25; j += BLK) s_x2[j] = x2g[j];
    }
    __syncthreads();

    // Ce = x2_row @ eps3  (stride-25 shared reads: 25 coprime 32 -> conflict-free)
    float ce[PP];
    {
        float m2[25];
        #pragma unroll
        for (int i = 0; i < 25; i++) m2[i] = s_x2[tid * 25 + i];
        #pragma unroll
        for (int i = 0; i < PP; i++) {
            float s = 0.f;
            #pragma unroll
            for (int j = 0; j < PP; j++) s += m2[i * PP + j] * e[j];
            ce[i] = s;
        }
        // curr_cov = omega + alpha*x2 + beta*Ce[j]^2 — write into own shared row
        // NOW so the 25 m2 registers die before the MLP (register pressure).
        float cb[PP];
        #pragma unroll
        for (int j = 0; j < PP; j++) cb[j] = 0.05f + 0.05f * ce[j] * ce[j];
        #pragma unroll
        for (int i = 0; i < PP; i++)
            #pragma unroll
            for (int j = 0; j < PP; j++)
                s_x2[tid * 25 + i * PP + j] = fmaf(0.1f, m2[i * PP + j], cb[j]);
    }

    // R = mu + Ce ; h = R then 3x tanh(h @ W_l^T)
    float r[PP], h[PP];
    #pragma unroll
    for (int i = 0; i < PP; i++) { r[i] = 0.01f + ce[i]; h[i] = r[i]; }
    #pragma unroll
    for (int l = 0; l < 3; l++) {
        float t[PP];
        #pragma unroll
        for (int i = 0; i < PP; i++) {
            float s = 0.f;
            #pragma unroll
            for (int j = 0; j < PP; j++) s += h[j] * s_w[l * 25 + i * PP + j];
            t[i] = tanh_fast(s);
        }
        #pragma unroll
        for (int i = 0; i < PP; i++) h[i] = t[i];
    }

    // softmax with max subtraction, single fast reciprocal
    float mx = h[0];
    #pragma unroll
    for (int i = 1; i < PP; i++) mx = fmaxf(mx, h[i]);
    float ssum = 0.f;
    float wgt[PP];
    #pragma unroll
    for (int i = 0; i < PP; i++) { wgt[i] = __expf(h[i] - mx); ssum += wgt[i]; }
    const float sinv = __fdividef(1.f, ssum);
    #pragma unroll
    for (int i = 0; i < PP; i++) wgt[i] *= sinv;

    // --- rebalance: semantics-exact replication of the 8-iter scan.
    // Once cont==false the reference freezes this row, so breaking is exact.
    float oldw[PP], nw[PP];
    #pragma unroll
    for (int i = 0; i < PP; i++) {
        oldw[i] = wgt[i];
        nw[i]  = fminf(fmaxf(wgt[i], LBV), UBV);
    }
    for (int it = 0; it < 8; it++) {
        float leftover = 0.f, msum = 0.f;
        float masked[PP];
        #pragma unroll
        for (int i = 0; i < PP; i++) {
            leftover += oldw[i] - nw[i];
            masked[i] = (nw[i] != UBV) ? nw[i] : 0.f;
            msum += masked[i];
        }
        const float scale = __fdividef(leftover, msum);
        float new2[PP];
        bool cont = false;
        #pragma unroll
        for (int i = 0; i < PP; i++) {
            new2[i] = fmaf(scale, masked[i], nw[i]);
            cont = cont || (new2[i] > UBV);
        }
        #pragma unroll
        for (int i = 0; i < PP; i++) {
            oldw[i] = new2[i];
            nw[i]   = cont ? fminf(fmaxf(new2[i], LBV), UBV) : new2[i];
        }
        if (!cont) break;
    }

    // wealth — evict-first store (output is never re-read; keep L2 for inputs)
    float wealth = 0.f;
    #pragma unroll
    for (int i = 0; i < PP; i++) wealth += x1v * nw[i] * (1.f + r[i]) * 1.03f;
    __stcs(out_wealth + base + tid, wealth);

    __syncthreads();
    // Coalesced evict-first store of curr_cov. Streaming the 54.6 MB of output
    // keeps the 65 MB input set resident in L2 across graph replays. Tail
    // placement is deliberate: the drain overlaps other resident CTAs' work.
    float* __restrict__ covg = out_cov + base * 25;
    if (vec_ok) {
        float4* __restrict__ c4 = (float4*)covg;
        const float4* s4 = (const float4*)s_x2;
        #pragma unroll
        for (int j = tid; j < BLK * 25 / 4; j += BLK) __stcs(c4 + j, s4[j]);
    } else {
        #pragma unroll 4
        for (int j = tid; j < BLK * 25; j += BLK) __stcs(covg + j, s_x2[j]);
    }
}

extern "C" void kernel_launch(void* const* d_in, const int* in_sizes, int n_in,
                              void* d_out, int out_size) {
    const float* x1  = (const float*)d_in[0];   // (B,)
    const float* x2  = (const float*)d_in[1];   // (B,5,5)
    const float* eps = (const float*)d_in[2];   // (4,B,5)
    const float* W   = (const float*)d_in[3];   // (4,3,5,5)
    float* out = (float*)d_out;                 // [wealth(B) | curr_cov(B*25)]

    const int B = in_sizes[0];
    float* out_wealth = out;
    float* out_cov    = out + B;

    // Vector path only if every float4-accessed global stream is 16B aligned.
    // (B is a multiple of BLK=256, so all in-kernel offsets preserve alignment.)
    const int vec_ok =
        (((uintptr_t)x2      & 15) == 0) &&
        (((uintptr_t)out_cov & 15) == 0) ? 1 : 0;

    portfolio_kernel<<<B / BLK, BLK>>>(x1, x2, eps, W, out_wealth, out_cov, B, vec_ok);
}

// round 14
// speedup vs baseline: 1.5452x; 1.0125x over previous
#include <cuda_runtime.h>
#include <cuda_bf16.h>
#include <cstdint>

#define PP 5
#define BLK 128              // threads per CTA; each thread handles 2 samples
#define SAMP (BLK * 2)       // 256 samples per CTA (same tile as R13)
#define UBV 0.5f
#define LBV 0.0f

__device__ __forceinline__ float tanh_fast(float x) {
    float y;
    asm("tanh.approx.f32 %0, %1;" : "=f"(y) : "f"(x));
    return y;
}

// R13 structure (committed: direct eps/x1 loads, float4 staging, in-place cov,
// evict-first tail store) + ILP=2: 128 threads x 2 samples. The two samples'
// MUFU/FMA chains are interleaved so the serial critical path (the measured
// bottleneck at issue=31%) always has an independent twin to issue behind.
// Natural register allocation (R9 lesson: never force).
__global__ __launch_bounds__(BLK) void portfolio_kernel(
    const float* __restrict__ x1,    // (B,)
    const float* __restrict__ x2,    // (B,5,5)
    const float* __restrict__ eps,   // (4,B,5)
    const float* __restrict__ W,     // (4,3,5,5)
    float* __restrict__ out_wealth,  // (B,)
    float* __restrict__ out_cov,     // (B,5,5)
    int B, int vec_ok)
{
    // 16B alignment REQUIRED for float4 shared paths (R2/R3 trap without it).
    __shared__ __align__(16) float s_x2[SAMP * 25];  // staged x2, rewritten as curr_cov
    __shared__ float s_w[75];                         // W[3]: 3 matrices of 5x5

    const int tid = threadIdx.x;
    const long long base = (long long)blockIdx.x * SAMP;
    const int ls0 = tid;             // local sample 0
    const int ls1 = tid + BLK;       // local sample 1

    // Direct loads for both samples — issued first so latency overlaps staging.
    const float x1v0 = x1[base + ls0];
    const float x1v1 = x1[base + ls1];
    const float* __restrict__ ep0 = eps + (long long)3 * B * PP + (base + ls0) * PP;
    const float* __restrict__ ep1 = eps + (long long)3 * B * PP + (base + ls1) * PP;
    float e0[PP], e1[PP];
    #pragma unroll
    for (int i = 0; i < PP; i++) e0[i] = ep0[i];
    #pragma unroll
    for (int i = 0; i < PP; i++) e1[i] = ep1[i];

    if (tid < 75) s_w[tid] = W[3 * 75 + tid];

    // Coalesced staging of this block's x2 tile (SAMP*25 = 6400 floats).
    const float* __restrict__ x2g = x2 + base * 25;
    if (vec_ok) {
        const float4* __restrict__ g4 = (const float4*)x2g;
        float4* s4 = (float4*)s_x2;
        #pragma unroll 4
        for (int j = tid; j < SAMP * 25 / 4; j += BLK) s4[j] = g4[j];
    } else {
        #pragma unroll 4
        for (int j = tid; j < SAMP * 25; j += BLK) s_x2[j] = x2g[j];
    }
    __syncthreads();

    // Ce + in-place cov for each sample, sequentially (keeps only one 25-reg
    // m2 tile live at a time — register pressure control).
    float ce0[PP], ce1[PP];
    #pragma unroll
    for (int s = 0; s < 2; s++) {
        const int ls = s == 0 ? ls0 : ls1;
        const float* ee = s == 0 ? e0 : e1;
        float* cc = s == 0 ? ce0 : ce1;
        float m2[25];
        #pragma unroll
        for (int i = 0; i < 25; i++) m2[i] = s_x2[ls * 25 + i];
        #pragma unroll
        for (int i = 0; i < PP; i++) {
            float acc = 0.f;
            #pragma unroll
            for (int j = 0; j < PP; j++) acc += m2[i * PP + j] * ee[j];
            cc[i] = acc;
        }
        float cb[PP];
        #pragma unroll
        for (int j = 0; j < PP; j++) cb[j] = 0.05f + 0.05f * cc[j] * cc[j];
        #pragma unroll
        for (int i = 0; i < PP; i++)
            #pragma unroll
            for (int j = 0; j < PP; j++)
                s_x2[ls * 25 + i * PP + j] = fmaf(0.1f, m2[i * PP + j], cb[j]);
    }

    // MLP: both samples interleaved — independent chains dual-issue.
    float r0[PP], r1[PP], h0[PP], h1[PP];
    #pragma unroll
    for (int i = 0; i < PP; i++) {
        r0[i] = 0.01f + ce0[i]; h0[i] = r0[i];
        r1[i] = 0.01f + ce1[i]; h1[i] = r1[i];
    }
    #pragma unroll
    for (int l = 0; l < 3; l++) {
        float t0[PP], t1[PP];
        #pragma unroll
        for (int i = 0; i < PP; i++) {
            float a0 = 0.f, a1 = 0.f;
            #pragma unroll
            for (int j = 0; j < PP; j++) {
                const float w = s_w[l * 25 + i * PP + j];
                a0 += h0[j] * w;
                a1 += h1[j] * w;
            }
            t0[i] = tanh_fast(a0);
            t1[i] = tanh_fast(a1);
        }
        #pragma unroll
        for (int i = 0; i < PP; i++) { h0[i] = t0[i]; h1[i] = t1[i]; }
    }

    // softmax, both samples interleaved
    float mx0 = h0[0], mx1 = h1[0];
    #pragma unroll
    for (int i = 1; i < PP; i++) { mx0 = fmaxf(mx0, h0[i]); mx1 = fmaxf(mx1, h1[i]); }
    float ss0 = 0.f, ss1 = 0.f;
    float w0[PP], w1[PP];
    #pragma unroll
    for (int i = 0; i < PP; i++) {
        w0[i] = __expf(h0[i] - mx0); ss0 += w0[i];
        w1[i] = __expf(h1[i] - mx1); ss1 += w1[i];
    }
    const float si0 = __fdividef(1.f, ss0);
    const float si1 = __fdividef(1.f, ss1);
    #pragma unroll
    for (int i = 0; i < PP; i++) { w0[i] *= si0; w1[i] *= si1; }

    // Rebalance per sample (branchy, usually 1 iter — kept scalar) + wealth.
    #pragma unroll
    for (int s = 0; s < 2; s++) {
        const float* ww = s == 0 ? w0 : w1;
        const float* rr = s == 0 ? r0 : r1;
        const float xv = s == 0 ? x1v0 : x1v1;
        const int ls = s == 0 ? ls0 : ls1;

        float oldw[PP], nw[PP];
        #pragma unroll
        for (int i = 0; i < PP; i++) {
            oldw[i] = ww[i];
            nw[i]  = fminf(fmaxf(ww[i], LBV), UBV);
        }
        for (int it = 0; it < 8; it++) {
            float leftover = 0.f, msum = 0.f;
            float masked[PP];
            #pragma unroll
            for (int i = 0; i < PP; i++) {
                leftover += oldw[i] - nw[i];
                masked[i] = (nw[i] != UBV) ? nw[i] : 0.f;
                msum += masked[i];
            }
            const float scale = __fdividef(leftover, msum);
            float new2[PP];
            bool cont = false;
            #pragma unroll
            for (int i = 0; i < PP; i++) {
                new2[i] = fmaf(scale, masked[i], nw[i]);
                cont = cont || (new2[i] > UBV);
            }
            #pragma unroll
            for (int i = 0; i < PP; i++) {
                oldw[i] = new2[i];
                nw[i]   = cont ? fminf(fmaxf(new2[i], LBV), UBV) : new2[i];
            }
            if (!cont) break;
        }

        float wealth = 0.f;
        #pragma unroll
        for (int i = 0; i < PP; i++) wealth += xv * nw[i] * (1.f + rr[i]) * 1.03f;
        __stcs(out_wealth + base + ls, wealth);
    }

    __syncthreads();
    // Coalesced evict-first tail store of curr_cov (tail placement preserves
    // inter-CTA drain/stage overlap; evict-first keeps inputs L2-resident
    // across graph replays).
    float* __restrict__ covg = out_cov + base * 25;
    if (vec_ok) {
        float4* __restrict__ c4 = (float4*)covg;
        const float4* s4 = (const float4*)s_x2;
        #pragma unroll 4
        for (int j = tid; j < SAMP * 25 / 4; j += BLK) __stcs(c4 + j, s4[j]);
    } else {
        #pragma unroll 4
        for (int j = tid; j < SAMP * 25; j += BLK) __stcs(covg + j, s_x2[j]);
    }
}

extern "C" void kernel_launch(void* const* d_in, const int* in_sizes, int n_in,
                              void* d_out, int out_size) {
    const float* x1  = (const float*)d_in[0];   // (B,)
    const float* x2  = (const float*)d_in[1];   // (B,5,5)
    const float* eps = (const float*)d_in[2];   // (4,B,5)
    const float* W   = (const float*)d_in[3];   // (4,3,5,5)
    float* out = (float*)d_out;                 // [wealth(B) | curr_cov(B*25)]

    const int B = in_sizes[0];
    float* out_wealth = out;
    float* out_cov    = out + B;

    const int vec_ok =
        (((uintptr_t)x2      & 15) == 0) &&
        (((uintptr_t)out_cov & 15) == 0) ? 1 : 0;

    portfolio_kernel<<<B / SAMP, BLK>>>(x1, x2, eps, W, out_wealth, out_cov, B, vec_ok);
}